// round 13
// baseline (speedup 1.0000x reference)
#include <cuda_runtime.h>
#include <math.h>

#define N_   32
#define C_   256
#define HW_  4096
#define G_   4
#define D_   64
#define MTOT 131072.0f
#define EPSW 1e-5f
#define LNEPS 1e-5f

typedef unsigned long long ull;

__device__ __forceinline__ void fma2(ull& d, ull a, ull b) {
    asm("fma.rn.f32x2 %0, %1, %2, %0;" : "+l"(d) : "l"(a), "l"(b));
}
__device__ __forceinline__ void add2(ull& d, ull a) {
    asm("add.rn.f32x2 %0, %0, %1;" : "+l"(d) : "l"(a));
}
__device__ __forceinline__ float2 u2f(ull v) {
    float2 r;
    asm("mov.b64 {%0,%1}, %2;" : "=f"(r.x), "=f"(r.y) : "l"(v));
    return r;
}
__device__ __forceinline__ ull dupf(float f) {
    ull r;
    asm("mov.b64 %0, {%1, %1};" : "=l"(r) : "f"(f));
    return r;
}
__device__ __forceinline__ void cpa16(void* sdst, const void* gsrc) {
    unsigned s = (unsigned)__cvta_generic_to_shared(sdst);
    asm volatile("cp.async.ca.shared.global [%0], [%1], 16;" :: "r"(s), "l"(gsrc));
}
#define CP_COMMIT() asm volatile("cp.async.commit_group;")
#define CP_WAIT0()  asm volatile("cp.async.wait_group 0;")

// ---------------- device scratch ----------------
__device__ float d_sum8  [8][N_*C_];
__device__ float d_sumsq8[8][N_*C_];
__device__ float d_gram [G_*D_*D_];
__device__ float d_a    [N_*C_];
__device__ float d_wP   [G_*D_*D_];

// ---------------- K0: zero gram accumulators ----------------
__global__ void k_zero() {
    int i = blockIdx.x * blockDim.x + threadIdx.x;
    if (i < G_*D_*D_) d_gram[i] = 0.0f;
}

// ---------------- K1: gram (SYMMETRIC) + fused row stats -------------------
// Round-12 version unchanged.
__global__ void __launch_bounds__(256, 3) k_gram(const float* __restrict__ X) {
    __shared__ __align__(16) float xs[2][D_ * 68];   // 34816 B
    __shared__ float rs[256], rs2[256];
    int chunk = blockIdx.x, n = blockIdx.y, g = blockIdx.z;
    int tid = threadIdx.x;
    int tx = tid & 15, ty = tid >> 4;
    int cs = tid & 63, q = tid >> 6;
    const float* base = X + ((size_t)n * C_ + (size_t)g * D_) * HW_ + chunk * 512;

    ull a00=0,a01=0,a02=0,a03=0,a11=0,a12=0,a13=0,a22=0,a23=0,a33=0;
    ull s_acc = 0ull, s2_acc = 0ull;

    {   // prologue: tile 0 -> buf 0
        #pragma unroll
        for (int k = 0; k < 4; ++k) {
            int pos = tid + k * 256;
            int c = pos >> 4, s4 = pos & 15;
            cpa16(&xs[0][c * 68 + s4 * 4], base + (size_t)c * HW_ + s4 * 4);
        }
        CP_COMMIT();
    }

    int buf = 0;
    for (int t = 0; t < 8; ++t) {
        CP_WAIT0();
        __syncthreads();
        if (t < 7) {
            const float* src = base + (t + 1) * 64;
            #pragma unroll
            for (int k = 0; k < 4; ++k) {
                int pos = tid + k * 256;
                int c = pos >> 4, s4 = pos & 15;
                cpa16(&xs[buf ^ 1][c * 68 + s4 * 4], src + (size_t)c * HW_ + s4 * 4);
            }
            CP_COMMIT();
        }
        const ulonglong2* xa = (const ulonglong2*)xs[buf];   // row stride 17 u2
        #pragma unroll 4
        for (int u = 0; u < 16; ++u) {
            ulonglong2 A0 = xa[(ty     )*17 + u], A1 = xa[(ty + 16)*17 + u];
            ulonglong2 A2 = xa[(ty + 32)*17 + u], A3 = xa[(ty + 48)*17 + u];
            ulonglong2 B0 = xa[(tx     )*17 + u], B1 = xa[(tx + 16)*17 + u];
            ulonglong2 B2 = xa[(tx + 32)*17 + u], B3 = xa[(tx + 48)*17 + u];
            fma2(a00, A0.x, B0.x); fma2(a00, A0.y, B0.y);
            fma2(a01, A0.x, B1.x); fma2(a01, A0.y, B1.y);
            fma2(a02, A0.x, B2.x); fma2(a02, A0.y, B2.y);
            fma2(a03, A0.x, B3.x); fma2(a03, A0.y, B3.y);
            fma2(a11, A1.x, B1.x); fma2(a11, A1.y, B1.y);
            fma2(a12, A1.x, B2.x); fma2(a12, A1.y, B2.y);
            fma2(a13, A1.x, B3.x); fma2(a13, A1.y, B3.y);
            fma2(a22, A2.x, B2.x); fma2(a22, A2.y, B2.y);
            fma2(a23, A2.x, B3.x); fma2(a23, A2.y, B3.y);
            fma2(a33, A3.x, B3.x); fma2(a33, A3.y, B3.y);
        }
        #pragma unroll
        for (int u = 4 * q; u < 4 * q + 4; ++u) {
            ulonglong2 v = xa[cs * 17 + u];
            add2(s_acc, v.x);  add2(s_acc, v.y);
            fma2(s2_acc, v.x, v.x); fma2(s2_acc, v.y, v.y);
        }
        buf ^= 1;
    }

    float2 sv = u2f(s_acc), s2v = u2f(s2_acc);
    rs[tid] = sv.x + sv.y; rs2[tid] = s2v.x + s2v.y;
    __syncthreads();
    if (tid < 64) {
        float a = rs[tid] + rs[tid+64] + rs[tid+128] + rs[tid+192];
        float b = rs2[tid] + rs2[tid+64] + rs2[tid+128] + rs2[tid+192];
        d_sum8  [chunk][n * C_ + g * 64 + tid] = a;
        d_sumsq8[chunk][n * C_ + g * 64 + tid] = b;
    }
    float* gp = d_gram + g * D_ * D_;
    {
        ull accs[10] = {a00,a01,a02,a03,a11,a12,a13,a22,a23,a33};
        const int II[10] = {0,0,0,0,1,1,1,2,2,3};
        const int JJ[10] = {0,1,2,3,1,2,3,2,3,3};
        #pragma unroll
        for (int k = 0; k < 10; ++k) {
            float2 f = u2f(accs[k]);
            float v = f.x + f.y;
            int r = ty + 16 * II[k], c = tx + 16 * JJ[k];
            atomicAdd(&gp[r * D_ + c], v);
            if (II[k] != JJ[k]) atomicAdd(&gp[c * D_ + r], v);
        }
    }
}

// ---------------- K2: fused newton (blocks 0-3) + mlp (blocks 4-35) --------
__device__ __forceinline__ void mm64t(float* Cm, const float* A, const float* B,
                                      int tx, int ty) {
    float acc[2][4] = {};
    #pragma unroll 4
    for (int k = 0; k < 64; ++k) {
        float a0 = A[ty*66 + k], a1 = A[(ty + 32)*66 + k];
        float b0 = B[k*66 + tx],      b1 = B[k*66 + tx + 16];
        float b2 = B[k*66 + tx + 32], b3 = B[k*66 + tx + 48];
        acc[0][0] += a0*b0; acc[0][1] += a0*b1; acc[0][2] += a0*b2; acc[0][3] += a0*b3;
        acc[1][0] += a1*b0; acc[1][1] += a1*b1; acc[1][2] += a1*b2; acc[1][3] += a1*b3;
    }
    #pragma unroll
    for (int i = 0; i < 2; ++i)
        #pragma unroll
        for (int j = 0; j < 4; ++j)
            Cm[(ty + 32*i)*66 + tx + 16*j] = acc[i][j];
}

__global__ void __launch_bounds__(512) k_tail(const float* __restrict__ fc1,
                                              const float* __restrict__ lng,
                                              const float* __restrict__ lnb,
                                              const float* __restrict__ fc2,
                                              const float* __restrict__ xw) {
    extern __shared__ float sm[];
    int blk = blockIdx.x, tid = threadIdx.x;
    float w = 1.0f / (1.0f + expf(-xw[0]));

    if (blk < 4) {
        float* SigN = sm;
        float* P    = sm + 4224;
        float* T1   = sm + 8448;
        float* T2   = sm + 12672;
        __shared__ float mu_s[64];
        __shared__ float s_invtr;
        int g = blk;
        int tx = tid & 15, ty = tid >> 4;

        if (tid < 64) {
            float m = 0.0f;
            #pragma unroll
            for (int ch = 0; ch < 8; ++ch)
                for (int n = 0; n < N_; ++n)
                    m += d_sum8[ch][n * C_ + g * 64 + tid];
            mu_s[tid] = m * (1.0f / MTOT);
        }
        __syncthreads();

        for (int t = 0; t < 8; ++t) {
            int idx = tid + t * 512;
            int d = idx >> 6, e = idx & 63;
            float v = EPSW * (d_gram[g*4096 + idx] - MTOT * mu_s[d] * mu_s[e]);
            if (d == e) v += 1.0f / MTOT;
            T1[d*66 + e] = v;
        }
        __syncthreads();
        if (tid == 0) {
            float tr = 0.0f;
            for (int d = 0; d < 64; ++d) tr += T1[d*66 + d];
            s_invtr = 1.0f / tr;
        }
        __syncthreads();
        float invtr = s_invtr;
        for (int t = 0; t < 8; ++t) {        // P1 = -0.5I + 1.5 SigN (P0 = I)
            int idx = tid + t * 512;
            int d = idx >> 6, e = idx & 63;
            float s = T1[d*66 + e] * invtr;
            SigN[d*66 + e] = s;
            P[d*66 + e] = 1.5f * s + ((d == e) ? -0.5f : 0.0f);
        }
        __syncthreads();
        for (int it = 0; it < 2; ++it) {
            mm64t(T1, P, P, tx, ty);     __syncthreads();
            mm64t(T2, T1, P, tx, ty);    __syncthreads();
            mm64t(T1, T2, SigN, tx, ty); __syncthreads();
            for (int t = 0; t < 8; ++t) {
                int idx = tid + t * 512;
                int d = idx >> 6, e = idx & 63;
                P[d*66 + e] = -0.5f * P[d*66 + e] + 1.5f * T1[d*66 + e];
            }
            __syncthreads();
        }
        for (int t = 0; t < 8; ++t) {
            int idx = tid + t * 512;
            int d = idx >> 6, e = idx & 63;
            d_wP[g*4096 + idx] = w * P[d*66 + e];
        }
    } else {
        int n = blk - 4;
        float* xv  = sm;          // 256
        float* h   = sm + 256;    // 64
        float* red = sm + 320;    // 512
        __shared__ float s_mu, s_inv, s_coef;
        int wi = tid >> 5, lane = tid & 31;

        float acc = 0.0f;
        for (int i = tid; i < N_*C_; i += 512) {
            float s = 0.0f, s2 = 0.0f;
            #pragma unroll
            for (int ch = 0; ch < 8; ++ch) { s += d_sum8[ch][i]; s2 += d_sumsq8[ch][i]; }
            acc += (s2 - s * s * (1.0f / HW_)) * (1.0f / (HW_ - 1));
        }
        red[tid] = acc;
        if (tid < 256) {
            int i = n * C_ + tid;
            float s = 0.0f, s2 = 0.0f;
            #pragma unroll
            for (int ch = 0; ch < 8; ++ch) { s += d_sum8[ch][i]; s2 += d_sumsq8[ch][i]; }
            xv[tid] = (s2 - s * s * (1.0f / HW_)) * (1.0f / (HW_ - 1));
        }
        __syncthreads();
        for (int off = 256; off; off >>= 1) {
            if (tid < off) red[tid] += red[tid + off];
            __syncthreads();
        }
        if (tid == 0)
            s_coef = (1.0f - w) / sqrtf(red[0] * (1.0f / (N_*C_)));

        #pragma unroll
        for (int jj = 0; jj < 4; ++jj) {
            int j = wi * 4 + jj;
            float a = 0.0f;
            #pragma unroll
            for (int s = 0; s < 8; ++s)
                a += fc1[j * C_ + lane + 32 * s] * xv[lane + 32 * s];
            #pragma unroll
            for (int o = 16; o; o >>= 1) a += __shfl_xor_sync(0xffffffffu, a, o);
            if (lane == 0) h[j] = a;
        }
        __syncthreads();

        if (wi == 0) {
            float v0 = h[lane], v1 = h[lane + 32];
            float s = v0 + v1, s2 = v0*v0 + v1*v1;
            #pragma unroll
            for (int o = 16; o; o >>= 1) {
                s  += __shfl_xor_sync(0xffffffffu, s,  o);
                s2 += __shfl_xor_sync(0xffffffffu, s2, o);
            }
            if (lane == 0) {
                float mu = s * (1.0f / D_);
                float var = s2 * (1.0f / D_) - mu * mu;
                s_mu = mu; s_inv = rsqrtf(var + LNEPS);
            }
        }
        __syncthreads();
        if (tid < 64) {
            float v = (h[tid] - s_mu) * s_inv * lng[tid] + lnb[tid];
            h[tid] = v > 0.0f ? v : 0.0f;
        }
        __syncthreads();

        float coef = s_coef;
        #pragma unroll
        for (int k = 0; k < 16; ++k) {
            int c = wi + 16 * k;
            float a = fc2[c * D_ + lane] * h[lane]
                    + fc2[c * D_ + lane + 32] * h[lane + 32];
            #pragma unroll
            for (int o = 16; o; o >>= 1) a += __shfl_xor_sync(0xffffffffu, a, o);
            if (lane == 0) d_a[n * C_ + c] = coef / (1.0f + expf(-a));
        }
    }
}

// ---------------- K3: out = (wP[g] + diag(a[n])) @ x -----------------------
// Occupancy experiment: 512 thr, launch_bounds(512,2) (<=64 regs) -> 32
// warps/SM (2x round-12). Warp w: d-block (w&7), position-half (w>>3); lane
// covers 4 positions -> acc[8][2]=32 regs. Same tile/smem as r12.
__global__ void __launch_bounds__(512, 2) k_apply(const float* __restrict__ X,
                                                  float* __restrict__ out) {
    extern __shared__ __align__(16) float sm2[];
    float* xs = sm2;                   // 64 x 256 floats = 64 KB
    float* Mt = sm2 + 16384;           // 64 x 68 floats (Mt[e][d] = M[d][e])
    int chunk = blockIdx.x, n = blockIdx.y, g = blockIdx.z;
    int tid = threadIdx.x;
    int lane = tid & 31, wrp = tid >> 5;
    int db = wrp & 7, ph = wrp >> 3;

    const float* base  = X   + ((size_t)n * C_ + (size_t)g * D_) * HW_ + chunk * 256;
    float*       obase = out + ((size_t)n * C_ + (size_t)g * D_) * HW_ + chunk * 256;

    // load full tile: 64 rows x 64 float4 (512 thr x 8)
    #pragma unroll
    for (int k = 0; k < 8; ++k) {
        int pos = tid + k * 512;
        int c = pos >> 6, s4 = pos & 63;
        cpa16(xs + c * 256 + s4 * 4, base + (size_t)c * HW_ + s4 * 4);
    }
    CP_COMMIT();

    // build Mt while the copy is in flight (512 thr x 8)
    for (int t = 0; t < 8; ++t) {
        int idx = tid + t * 512;
        int d = idx & 63, e = idx >> 6;
        float v = d_wP[g*4096 + d * 64 + e];
        if (d == e) v += d_a[n * C_ + g * 64 + d];
        Mt[e * 68 + d] = v;
    }

    CP_WAIT0();
    __syncthreads();

    ull acc[8][2] = {};
    const float4* ma = (const float4*)Mt;        // row stride 17 float4
    #pragma unroll 4
    for (int e = 0; e < 64; ++e) {
        float4 m0 = ma[e * 17 + 2 * db];         // M[8db..8db+3][e]
        float4 m1 = ma[e * 17 + 2 * db + 1];     // M[8db+4..8db+7][e]
        const ulonglong2* xrow = (const ulonglong2*)(xs + e * 256);
        ulonglong2 B = xrow[ph * 32 + lane];     // pos 128*ph + 4*lane
        ull a0 = dupf(m0.x), a1 = dupf(m0.y), a2 = dupf(m0.z), a3 = dupf(m0.w);
        ull a4 = dupf(m1.x), a5 = dupf(m1.y), a6 = dupf(m1.z), a7 = dupf(m1.w);
        fma2(acc[0][0], a0, B.x); fma2(acc[0][1], a0, B.y);
        fma2(acc[1][0], a1, B.x); fma2(acc[1][1], a1, B.y);
        fma2(acc[2][0], a2, B.x); fma2(acc[2][1], a2, B.y);
        fma2(acc[3][0], a3, B.x); fma2(acc[3][1], a3, B.y);
        fma2(acc[4][0], a4, B.x); fma2(acc[4][1], a4, B.y);
        fma2(acc[5][0], a5, B.x); fma2(acc[5][1], a5, B.y);
        fma2(acc[6][0], a6, B.x); fma2(acc[6][1], a6, B.y);
        fma2(acc[7][0], a7, B.x); fma2(acc[7][1], a7, B.y);
    }

    #pragma unroll
    for (int j = 0; j < 8; ++j) {
        int d = 8 * db + j;
        float* drow = obase + (size_t)d * HW_;
        float2 r0 = u2f(acc[j][0]), r1 = u2f(acc[j][1]);
        *(float4*)(drow + 128 * ph + 4 * lane) = make_float4(r0.x, r0.y, r1.x, r1.y);
    }
}

// ---------------- launch ----------------
extern "C" void kernel_launch(void* const* d_in, const int* in_sizes, int n_in,
                              void* d_out, int out_size) {
    const float* X   = (const float*)d_in[0];
    const float* fc1 = (const float*)d_in[1];
    const float* lng = (const float*)d_in[2];
    const float* lnb = (const float*)d_in[3];
    const float* fc2 = (const float*)d_in[4];
    const float* xw  = (const float*)d_in[5];
    float* out = (float*)d_out;

    static bool attr_set = false;
    if (!attr_set) {
        cudaFuncSetAttribute(k_tail,  cudaFuncAttributeMaxDynamicSharedMemorySize, 69632);
        cudaFuncSetAttribute(k_apply, cudaFuncAttributeMaxDynamicSharedMemorySize, 83968);
        attr_set = true;
    }

    k_zero <<<64, 256>>>();
    k_gram <<<dim3(8, 32, 4), 256>>>(X);
    k_tail <<<36, 512, 69632>>>(fc1, lng, lnb, fc2, xw);
    k_apply<<<dim3(16, 32, 4), 512, 82944>>>(X, out);
}

// round 14
// speedup vs baseline: 1.0368x; 1.0368x over previous
#include <cuda_runtime.h>
#include <math.h>
#include <stdint.h>

#define N_   32
#define C_   256
#define HW_  4096
#define G_   4
#define D_   64
#define MTOT 131072.0f
#define EPSW 1e-5f
#define LNEPS 1e-5f

typedef unsigned long long ull;

__device__ __forceinline__ void fma2(ull& d, ull a, ull b) {
    asm("fma.rn.f32x2 %0, %1, %2, %0;" : "+l"(d) : "l"(a), "l"(b));
}
__device__ __forceinline__ void add2(ull& d, ull a) {
    asm("add.rn.f32x2 %0, %0, %1;" : "+l"(d) : "l"(a));
}
__device__ __forceinline__ float2 u2f(ull v) {
    float2 r;
    asm("mov.b64 {%0,%1}, %2;" : "=f"(r.x), "=f"(r.y) : "l"(v));
    return r;
}
__device__ __forceinline__ ull dupf(float f) {
    ull r;
    asm("mov.b64 %0, {%1, %1};" : "=l"(r) : "f"(f));
    return r;
}
__device__ __forceinline__ void cpa16(void* sdst, const void* gsrc) {
    unsigned s = (unsigned)__cvta_generic_to_shared(sdst);
    asm volatile("cp.async.ca.shared.global [%0], [%1], 16;" :: "r"(s), "l"(gsrc));
}
#define CP_COMMIT() asm volatile("cp.async.commit_group;")
#define CP_WAIT0()  asm volatile("cp.async.wait_group 0;")

// ---------------- device scratch ----------------
__device__ float d_sum8  [8][N_*C_];
__device__ float d_sumsq8[8][N_*C_];
__device__ float d_gram [G_*D_*D_];
__device__ float d_a    [N_*C_];
__device__ float d_wP   [G_*D_*D_];

// ---------------- K0: zero gram accumulators ----------------
__global__ void k_zero() {
    int i = blockIdx.x * blockDim.x + threadIdx.x;
    if (i < G_*D_*D_) d_gram[i] = 0.0f;
}

// ---------------- K1: gram (SYMMETRIC) + fused row stats -------------------
// Round-12 version unchanged.
__global__ void __launch_bounds__(256, 3) k_gram(const float* __restrict__ X) {
    __shared__ __align__(16) float xs[2][D_ * 68];   // 34816 B
    __shared__ float rs[256], rs2[256];
    int chunk = blockIdx.x, n = blockIdx.y, g = blockIdx.z;
    int tid = threadIdx.x;
    int tx = tid & 15, ty = tid >> 4;
    int cs = tid & 63, q = tid >> 6;
    const float* base = X + ((size_t)n * C_ + (size_t)g * D_) * HW_ + chunk * 512;

    ull a00=0,a01=0,a02=0,a03=0,a11=0,a12=0,a13=0,a22=0,a23=0,a33=0;
    ull s_acc = 0ull, s2_acc = 0ull;

    {   // prologue: tile 0 -> buf 0
        #pragma unroll
        for (int k = 0; k < 4; ++k) {
            int pos = tid + k * 256;
            int c = pos >> 4, s4 = pos & 15;
            cpa16(&xs[0][c * 68 + s4 * 4], base + (size_t)c * HW_ + s4 * 4);
        }
        CP_COMMIT();
    }

    int buf = 0;
    for (int t = 0; t < 8; ++t) {
        CP_WAIT0();
        __syncthreads();
        if (t < 7) {
            const float* src = base + (t + 1) * 64;
            #pragma unroll
            for (int k = 0; k < 4; ++k) {
                int pos = tid + k * 256;
                int c = pos >> 4, s4 = pos & 15;
                cpa16(&xs[buf ^ 1][c * 68 + s4 * 4], src + (size_t)c * HW_ + s4 * 4);
            }
            CP_COMMIT();
        }
        const ulonglong2* xa = (const ulonglong2*)xs[buf];   // row stride 17 u2
        #pragma unroll 4
        for (int u = 0; u < 16; ++u) {
            ulonglong2 A0 = xa[(ty     )*17 + u], A1 = xa[(ty + 16)*17 + u];
            ulonglong2 A2 = xa[(ty + 32)*17 + u], A3 = xa[(ty + 48)*17 + u];
            ulonglong2 B0 = xa[(tx     )*17 + u], B1 = xa[(tx + 16)*17 + u];
            ulonglong2 B2 = xa[(tx + 32)*17 + u], B3 = xa[(tx + 48)*17 + u];
            fma2(a00, A0.x, B0.x); fma2(a00, A0.y, B0.y);
            fma2(a01, A0.x, B1.x); fma2(a01, A0.y, B1.y);
            fma2(a02, A0.x, B2.x); fma2(a02, A0.y, B2.y);
            fma2(a03, A0.x, B3.x); fma2(a03, A0.y, B3.y);
            fma2(a11, A1.x, B1.x); fma2(a11, A1.y, B1.y);
            fma2(a12, A1.x, B2.x); fma2(a12, A1.y, B2.y);
            fma2(a13, A1.x, B3.x); fma2(a13, A1.y, B3.y);
            fma2(a22, A2.x, B2.x); fma2(a22, A2.y, B2.y);
            fma2(a23, A2.x, B3.x); fma2(a23, A2.y, B3.y);
            fma2(a33, A3.x, B3.x); fma2(a33, A3.y, B3.y);
        }
        #pragma unroll
        for (int u = 4 * q; u < 4 * q + 4; ++u) {
            ulonglong2 v = xa[cs * 17 + u];
            add2(s_acc, v.x);  add2(s_acc, v.y);
            fma2(s2_acc, v.x, v.x); fma2(s2_acc, v.y, v.y);
        }
        buf ^= 1;
    }

    float2 sv = u2f(s_acc), s2v = u2f(s2_acc);
    rs[tid] = sv.x + sv.y; rs2[tid] = s2v.x + s2v.y;
    __syncthreads();
    if (tid < 64) {
        float a = rs[tid] + rs[tid+64] + rs[tid+128] + rs[tid+192];
        float b = rs2[tid] + rs2[tid+64] + rs2[tid+128] + rs2[tid+192];
        d_sum8  [chunk][n * C_ + g * 64 + tid] = a;
        d_sumsq8[chunk][n * C_ + g * 64 + tid] = b;
    }
    float* gp = d_gram + g * D_ * D_;
    {
        ull accs[10] = {a00,a01,a02,a03,a11,a12,a13,a22,a23,a33};
        const int II[10] = {0,0,0,0,1,1,1,2,2,3};
        const int JJ[10] = {0,1,2,3,1,2,3,2,3,3};
        #pragma unroll
        for (int k = 0; k < 10; ++k) {
            float2 f = u2f(accs[k]);
            float v = f.x + f.y;
            int r = ty + 16 * II[k], c = tx + 16 * JJ[k];
            atomicAdd(&gp[r * D_ + c], v);
            if (II[k] != JJ[k]) atomicAdd(&gp[c * D_ + r], v);
        }
    }
}

// ---------------- K2: fused newton (blocks 0-3) + mlp (blocks 4-35) --------
__device__ __forceinline__ void mm64t(float* Cm, const float* A, const float* B,
                                      int tx, int ty) {
    float acc[2][4] = {};
    #pragma unroll 4
    for (int k = 0; k < 64; ++k) {
        float a0 = A[ty*66 + k], a1 = A[(ty + 32)*66 + k];
        float b0 = B[k*66 + tx],      b1 = B[k*66 + tx + 16];
        float b2 = B[k*66 + tx + 32], b3 = B[k*66 + tx + 48];
        acc[0][0] += a0*b0; acc[0][1] += a0*b1; acc[0][2] += a0*b2; acc[0][3] += a0*b3;
        acc[1][0] += a1*b0; acc[1][1] += a1*b1; acc[1][2] += a1*b2; acc[1][3] += a1*b3;
    }
    #pragma unroll
    for (int i = 0; i < 2; ++i)
        #pragma unroll
        for (int j = 0; j < 4; ++j)
            Cm[(ty + 32*i)*66 + tx + 16*j] = acc[i][j];
}

__global__ void __launch_bounds__(512) k_tail(const float* __restrict__ fc1,
                                              const float* __restrict__ lng,
                                              const float* __restrict__ lnb,
                                              const float* __restrict__ fc2,
                                              const float* __restrict__ xw) {
    extern __shared__ float sm[];
    int blk = blockIdx.x, tid = threadIdx.x;
    float w = 1.0f / (1.0f + expf(-xw[0]));

    if (blk < 4) {
        float* SigN = sm;
        float* P    = sm + 4224;
        float* T1   = sm + 8448;
        float* T2   = sm + 12672;
        __shared__ float mu_s[64];
        __shared__ float s_invtr;
        int g = blk;
        int tx = tid & 15, ty = tid >> 4;

        if (tid < 64) {
            float m = 0.0f;
            #pragma unroll
            for (int ch = 0; ch < 8; ++ch)
                for (int n = 0; n < N_; ++n)
                    m += d_sum8[ch][n * C_ + g * 64 + tid];
            mu_s[tid] = m * (1.0f / MTOT);
        }
        __syncthreads();

        for (int t = 0; t < 8; ++t) {
            int idx = tid + t * 512;
            int d = idx >> 6, e = idx & 63;
            float v = EPSW * (d_gram[g*4096 + idx] - MTOT * mu_s[d] * mu_s[e]);
            if (d == e) v += 1.0f / MTOT;
            T1[d*66 + e] = v;
        }
        __syncthreads();
        if (tid == 0) {
            float tr = 0.0f;
            for (int d = 0; d < 64; ++d) tr += T1[d*66 + d];
            s_invtr = 1.0f / tr;
        }
        __syncthreads();
        float invtr = s_invtr;
        for (int t = 0; t < 8; ++t) {        // P1 = -0.5I + 1.5 SigN (P0 = I)
            int idx = tid + t * 512;
            int d = idx >> 6, e = idx & 63;
            float s = T1[d*66 + e] * invtr;
            SigN[d*66 + e] = s;
            P[d*66 + e] = 1.5f * s + ((d == e) ? -0.5f : 0.0f);
        }
        __syncthreads();
        for (int it = 0; it < 2; ++it) {
            mm64t(T1, P, P, tx, ty);     __syncthreads();
            mm64t(T2, T1, P, tx, ty);    __syncthreads();
            mm64t(T1, T2, SigN, tx, ty); __syncthreads();
            for (int t = 0; t < 8; ++t) {
                int idx = tid + t * 512;
                int d = idx >> 6, e = idx & 63;
                P[d*66 + e] = -0.5f * P[d*66 + e] + 1.5f * T1[d*66 + e];
            }
            __syncthreads();
        }
        for (int t = 0; t < 8; ++t) {
            int idx = tid + t * 512;
            int d = idx >> 6, e = idx & 63;
            d_wP[g*4096 + idx] = w * P[d*66 + e];
        }
    } else {
        int n = blk - 4;
        float* xv  = sm;          // 256
        float* h   = sm + 256;    // 64
        float* red = sm + 320;    // 512
        __shared__ float s_mu, s_inv, s_coef;
        int wi = tid >> 5, lane = tid & 31;

        float acc = 0.0f;
        for (int i = tid; i < N_*C_; i += 512) {
            float s = 0.0f, s2 = 0.0f;
            #pragma unroll
            for (int ch = 0; ch < 8; ++ch) { s += d_sum8[ch][i]; s2 += d_sumsq8[ch][i]; }
            acc += (s2 - s * s * (1.0f / HW_)) * (1.0f / (HW_ - 1));
        }
        red[tid] = acc;
        if (tid < 256) {
            int i = n * C_ + tid;
            float s = 0.0f, s2 = 0.0f;
            #pragma unroll
            for (int ch = 0; ch < 8; ++ch) { s += d_sum8[ch][i]; s2 += d_sumsq8[ch][i]; }
            xv[tid] = (s2 - s * s * (1.0f / HW_)) * (1.0f / (HW_ - 1));
        }
        __syncthreads();
        for (int off = 256; off; off >>= 1) {
            if (tid < off) red[tid] += red[tid + off];
            __syncthreads();
        }
        if (tid == 0)
            s_coef = (1.0f - w) / sqrtf(red[0] * (1.0f / (N_*C_)));

        #pragma unroll
        for (int jj = 0; jj < 4; ++jj) {
            int j = wi * 4 + jj;
            float a = 0.0f;
            #pragma unroll
            for (int s = 0; s < 8; ++s)
                a += fc1[j * C_ + lane + 32 * s] * xv[lane + 32 * s];
            #pragma unroll
            for (int o = 16; o; o >>= 1) a += __shfl_xor_sync(0xffffffffu, a, o);
            if (lane == 0) h[j] = a;
        }
        __syncthreads();

        if (wi == 0) {
            float v0 = h[lane], v1 = h[lane + 32];
            float s = v0 + v1, s2 = v0*v0 + v1*v1;
            #pragma unroll
            for (int o = 16; o; o >>= 1) {
                s  += __shfl_xor_sync(0xffffffffu, s,  o);
                s2 += __shfl_xor_sync(0xffffffffu, s2, o);
            }
            if (lane == 0) {
                float mu = s * (1.0f / D_);
                float var = s2 * (1.0f / D_) - mu * mu;
                s_mu = mu; s_inv = rsqrtf(var + LNEPS);
            }
        }
        __syncthreads();
        if (tid < 64) {
            float v = (h[tid] - s_mu) * s_inv * lng[tid] + lnb[tid];
            h[tid] = v > 0.0f ? v : 0.0f;
        }
        __syncthreads();

        float coef = s_coef;
        #pragma unroll
        for (int k = 0; k < 16; ++k) {
            int c = wi + 16 * k;
            float a = fc2[c * D_ + lane] * h[lane]
                    + fc2[c * D_ + lane + 32] * h[lane + 32];
            #pragma unroll
            for (int o = 16; o; o >>= 1) a += __shfl_xor_sync(0xffffffffu, a, o);
            if (lane == 0) d_a[n * C_ + c] = coef / (1.0f + expf(-a));
        }
    }
}

// ---------------- K3: out = (wP[g] + diag(a[n])) @ x -----------------------
// Round-12 compute exactly; ONE change: tile load via 64 x cp.async.bulk
// (1KB contiguous rows) + mbarrier, replacing 4096 per-CTA LDGSTS. Removes
// the cp.async issue cost + L1TEX fill-side wavefronts.
__global__ void __launch_bounds__(256, 2) k_apply(const float* __restrict__ X,
                                                  float* __restrict__ out) {
    extern __shared__ __align__(16) float sm2[];
    float* xs = sm2;                   // 64 x 256 floats = 64 KB, rows contiguous
    float* Mt = sm2 + 16384;           // 64 x 68 floats (Mt[e][d] = M[d][e])
    __shared__ __align__(8) uint64_t mbar;
    int chunk = blockIdx.x, n = blockIdx.y, g = blockIdx.z;
    int tid = threadIdx.x;
    int lane = tid & 31, wrp = tid >> 5;

    const float* base  = X   + ((size_t)n * C_ + (size_t)g * D_) * HW_ + chunk * 256;
    float*       obase = out + ((size_t)n * C_ + (size_t)g * D_) * HW_ + chunk * 256;

    unsigned mb = (unsigned)__cvta_generic_to_shared(&mbar);
    if (tid == 0)
        asm volatile("mbarrier.init.shared.b64 [%0], 1;" :: "r"(mb) : "memory");
    __syncthreads();
    if (tid == 0)
        asm volatile("mbarrier.arrive.expect_tx.shared.b64 _, [%0], %1;"
                     :: "r"(mb), "r"(65536u) : "memory");
    if (tid < 64) {
        unsigned dst = (unsigned)__cvta_generic_to_shared(xs + tid * 256);
        const float* src = base + (size_t)tid * HW_;
        asm volatile(
            "cp.async.bulk.shared::cta.global.mbarrier::complete_tx::bytes "
            "[%0], [%1], %2, [%3];"
            :: "r"(dst), "l"(src), "r"(1024u), "r"(mb) : "memory");
    }

    // build Mt while the bulk copies are in flight
    for (int t = 0; t < 16; ++t) {
        int idx = tid + t * 256;
        int d = idx & 63, e = idx >> 6;
        float v = d_wP[g*4096 + d * 64 + e];
        if (d == e) v += d_a[n * C_ + g * 64 + d];
        Mt[e * 68 + d] = v;
    }

    {   // wait for tile (phase 0)
        unsigned done;
        do {
            asm volatile(
                "{\n\t.reg .pred p;\n\t"
                "mbarrier.try_wait.parity.acquire.cta.shared::cta.b64 p, [%1], %2;\n\t"
                "selp.b32 %0, 1, 0, p;\n\t}"
                : "=r"(done) : "r"(mb), "r"(0u) : "memory");
        } while (!done);
    }
    __syncthreads();

    ull acc[8][4] = {};
    const float4* ma = (const float4*)Mt;        // row stride 17 float4
    #pragma unroll 4
    for (int e = 0; e < 64; ++e) {
        float4 m0 = ma[e * 17 + 2 * wrp];        // M[8w..8w+3][e]
        float4 m1 = ma[e * 17 + 2 * wrp + 1];    // M[8w+4..8w+7][e]
        const ulonglong2* xrow = (const ulonglong2*)(xs + e * 256);
        ulonglong2 B0 = xrow[lane];              // pos 4l..4l+3
        ulonglong2 B1 = xrow[lane + 32];         // pos 128+4l..128+4l+3
        ull a0 = dupf(m0.x), a1 = dupf(m0.y), a2 = dupf(m0.z), a3 = dupf(m0.w);
        ull a4 = dupf(m1.x), a5 = dupf(m1.y), a6 = dupf(m1.z), a7 = dupf(m1.w);
        fma2(acc[0][0], a0, B0.x); fma2(acc[0][1], a0, B0.y);
        fma2(acc[0][2], a0, B1.x); fma2(acc[0][3], a0, B1.y);
        fma2(acc[1][0], a1, B0.x); fma2(acc[1][1], a1, B0.y);
        fma2(acc[1][2], a1, B1.x); fma2(acc[1][3], a1, B1.y);
        fma2(acc[2][0], a2, B0.x); fma2(acc[2][1], a2, B0.y);
        fma2(acc[2][2], a2, B1.x); fma2(acc[2][3], a2, B1.y);
        fma2(acc[3][0], a3, B0.x); fma2(acc[3][1], a3, B0.y);
        fma2(acc[3][2], a3, B1.x); fma2(acc[3][3], a3, B1.y);
        fma2(acc[4][0], a4, B0.x); fma2(acc[4][1], a4, B0.y);
        fma2(acc[4][2], a4, B1.x); fma2(acc[4][3], a4, B1.y);
        fma2(acc[5][0], a5, B0.x); fma2(acc[5][1], a5, B0.y);
        fma2(acc[5][2], a5, B1.x); fma2(acc[5][3], a5, B1.y);
        fma2(acc[6][0], a6, B0.x); fma2(acc[6][1], a6, B0.y);
        fma2(acc[6][2], a6, B1.x); fma2(acc[6][3], a6, B1.y);
        fma2(acc[7][0], a7, B0.x); fma2(acc[7][1], a7, B0.y);
        fma2(acc[7][2], a7, B1.x); fma2(acc[7][3], a7, B1.y);
    }

    #pragma unroll
    for (int j = 0; j < 8; ++j) {
        int d = 8 * wrp + j;
        float* drow = obase + (size_t)d * HW_;
        float2 r0 = u2f(acc[j][0]), r1 = u2f(acc[j][1]);
        float2 r2 = u2f(acc[j][2]), r3 = u2f(acc[j][3]);
        *(float4*)(drow + 4 * lane)       = make_float4(r0.x, r0.y, r1.x, r1.y);
        *(float4*)(drow + 128 + 4 * lane) = make_float4(r2.x, r2.y, r3.x, r3.y);
    }
}

// ---------------- launch ----------------
extern "C" void kernel_launch(void* const* d_in, const int* in_sizes, int n_in,
                              void* d_out, int out_size) {
    const float* X   = (const float*)d_in[0];
    const float* fc1 = (const float*)d_in[1];
    const float* lng = (const float*)d_in[2];
    const float* lnb = (const float*)d_in[3];
    const float* fc2 = (const float*)d_in[4];
    const float* xw  = (const float*)d_in[5];
    float* out = (float*)d_out;

    static bool attr_set = false;
    if (!attr_set) {
        cudaFuncSetAttribute(k_tail,  cudaFuncAttributeMaxDynamicSharedMemorySize, 69632);
        cudaFuncSetAttribute(k_apply, cudaFuncAttributeMaxDynamicSharedMemorySize, 83968);
        attr_set = true;
    }

    k_zero <<<64, 256>>>();
    k_gram <<<dim3(8, 32, 4), 256>>>(X);
    k_tail <<<36, 512, 69632>>>(fc1, lng, lnb, fc2, xw);
    k_apply<<<dim3(16, 32, 4), 256, 82944>>>(X, out);
}

// round 15
// speedup vs baseline: 1.0434x; 1.0063x over previous
#include <cuda_runtime.h>
#include <math.h>
#include <stdint.h>

#define N_   32
#define C_   256
#define HW_  4096
#define G_   4
#define D_   64
#define MTOT 131072.0f
#define EPSW 1e-5f
#define LNEPS 1e-5f

typedef unsigned long long ull;

__device__ __forceinline__ void fma2(ull& d, ull a, ull b) {
    asm("fma.rn.f32x2 %0, %1, %2, %0;" : "+l"(d) : "l"(a), "l"(b));
}
__device__ __forceinline__ void add2(ull& d, ull a) {
    asm("add.rn.f32x2 %0, %0, %1;" : "+l"(d) : "l"(a));
}
__device__ __forceinline__ float2 u2f(ull v) {
    float2 r;
    asm("mov.b64 {%0,%1}, %2;" : "=f"(r.x), "=f"(r.y) : "l"(v));
    return r;
}
__device__ __forceinline__ ull dupf(float f) {
    ull r;
    asm("mov.b64 %0, {%1, %1};" : "=l"(r) : "f"(f));
    return r;
}
__device__ __forceinline__ void cpa16(void* sdst, const void* gsrc) {
    unsigned s = (unsigned)__cvta_generic_to_shared(sdst);
    asm volatile("cp.async.ca.shared.global [%0], [%1], 16;" :: "r"(s), "l"(gsrc));
}
#define CP_COMMIT() asm volatile("cp.async.commit_group;")
#define CP_WAIT0()  asm volatile("cp.async.wait_group 0;")

__device__ __forceinline__ void mbar_wait(unsigned mb, unsigned parity) {
    unsigned done;
    do {
        asm volatile(
            "{\n\t.reg .pred p;\n\t"
            "mbarrier.try_wait.parity.acquire.cta.shared::cta.b64 p, [%1], %2;\n\t"
            "selp.b32 %0, 1, 0, p;\n\t}"
            : "=r"(done) : "r"(mb), "r"(parity) : "memory");
    } while (!done);
}

// ---------------- device scratch ----------------
__device__ float d_sum8  [8][N_*C_];
__device__ float d_sumsq8[8][N_*C_];
__device__ float d_gram [G_*D_*D_];
__device__ float d_a    [N_*C_];
__device__ float d_wP   [G_*D_*D_];

// ---------------- K0: zero gram accumulators ----------------
__global__ void k_zero() {
    int i = blockIdx.x * blockDim.x + threadIdx.x;
    if (i < G_*D_*D_) d_gram[i] = 0.0f;
}

// ---------------- K1: gram (SYMMETRIC) + fused row stats -------------------
// Round-12 version unchanged.
__global__ void __launch_bounds__(256, 3) k_gram(const float* __restrict__ X) {
    __shared__ __align__(16) float xs[2][D_ * 68];   // 34816 B
    __shared__ float rs[256], rs2[256];
    int chunk = blockIdx.x, n = blockIdx.y, g = blockIdx.z;
    int tid = threadIdx.x;
    int tx = tid & 15, ty = tid >> 4;
    int cs = tid & 63, q = tid >> 6;
    const float* base = X + ((size_t)n * C_ + (size_t)g * D_) * HW_ + chunk * 512;

    ull a00=0,a01=0,a02=0,a03=0,a11=0,a12=0,a13=0,a22=0,a23=0,a33=0;
    ull s_acc = 0ull, s2_acc = 0ull;

    {   // prologue: tile 0 -> buf 0
        #pragma unroll
        for (int k = 0; k < 4; ++k) {
            int pos = tid + k * 256;
            int c = pos >> 4, s4 = pos & 15;
            cpa16(&xs[0][c * 68 + s4 * 4], base + (size_t)c * HW_ + s4 * 4);
        }
        CP_COMMIT();
    }

    int buf = 0;
    for (int t = 0; t < 8; ++t) {
        CP_WAIT0();
        __syncthreads();
        if (t < 7) {
            const float* src = base + (t + 1) * 64;
            #pragma unroll
            for (int k = 0; k < 4; ++k) {
                int pos = tid + k * 256;
                int c = pos >> 4, s4 = pos & 15;
                cpa16(&xs[buf ^ 1][c * 68 + s4 * 4], src + (size_t)c * HW_ + s4 * 4);
            }
            CP_COMMIT();
        }
        const ulonglong2* xa = (const ulonglong2*)xs[buf];   // row stride 17 u2
        #pragma unroll 4
        for (int u = 0; u < 16; ++u) {
            ulonglong2 A0 = xa[(ty     )*17 + u], A1 = xa[(ty + 16)*17 + u];
            ulonglong2 A2 = xa[(ty + 32)*17 + u], A3 = xa[(ty + 48)*17 + u];
            ulonglong2 B0 = xa[(tx     )*17 + u], B1 = xa[(tx + 16)*17 + u];
            ulonglong2 B2 = xa[(tx + 32)*17 + u], B3 = xa[(tx + 48)*17 + u];
            fma2(a00, A0.x, B0.x); fma2(a00, A0.y, B0.y);
            fma2(a01, A0.x, B1.x); fma2(a01, A0.y, B1.y);
            fma2(a02, A0.x, B2.x); fma2(a02, A0.y, B2.y);
            fma2(a03, A0.x, B3.x); fma2(a03, A0.y, B3.y);
            fma2(a11, A1.x, B1.x); fma2(a11, A1.y, B1.y);
            fma2(a12, A1.x, B2.x); fma2(a12, A1.y, B2.y);
            fma2(a13, A1.x, B3.x); fma2(a13, A1.y, B3.y);
            fma2(a22, A2.x, B2.x); fma2(a22, A2.y, B2.y);
            fma2(a23, A2.x, B3.x); fma2(a23, A2.y, B3.y);
            fma2(a33, A3.x, B3.x); fma2(a33, A3.y, B3.y);
        }
        #pragma unroll
        for (int u = 4 * q; u < 4 * q + 4; ++u) {
            ulonglong2 v = xa[cs * 17 + u];
            add2(s_acc, v.x);  add2(s_acc, v.y);
            fma2(s2_acc, v.x, v.x); fma2(s2_acc, v.y, v.y);
        }
        buf ^= 1;
    }

    float2 sv = u2f(s_acc), s2v = u2f(s2_acc);
    rs[tid] = sv.x + sv.y; rs2[tid] = s2v.x + s2v.y;
    __syncthreads();
    if (tid < 64) {
        float a = rs[tid] + rs[tid+64] + rs[tid+128] + rs[tid+192];
        float b = rs2[tid] + rs2[tid+64] + rs2[tid+128] + rs2[tid+192];
        d_sum8  [chunk][n * C_ + g * 64 + tid] = a;
        d_sumsq8[chunk][n * C_ + g * 64 + tid] = b;
    }
    float* gp = d_gram + g * D_ * D_;
    {
        ull accs[10] = {a00,a01,a02,a03,a11,a12,a13,a22,a23,a33};
        const int II[10] = {0,0,0,0,1,1,1,2,2,3};
        const int JJ[10] = {0,1,2,3,1,2,3,2,3,3};
        #pragma unroll
        for (int k = 0; k < 10; ++k) {
            float2 f = u2f(accs[k]);
            float v = f.x + f.y;
            int r = ty + 16 * II[k], c = tx + 16 * JJ[k];
            atomicAdd(&gp[r * D_ + c], v);
            if (II[k] != JJ[k]) atomicAdd(&gp[c * D_ + r], v);
        }
    }
}

// ---------------- K2: fused newton (blocks 0-3) + mlp (blocks 4-35) --------
__device__ __forceinline__ void mm64t(float* Cm, const float* A, const float* B,
                                      int tx, int ty) {
    float acc[2][4] = {};
    #pragma unroll 4
    for (int k = 0; k < 64; ++k) {
        float a0 = A[ty*66 + k], a1 = A[(ty + 32)*66 + k];
        float b0 = B[k*66 + tx],      b1 = B[k*66 + tx + 16];
        float b2 = B[k*66 + tx + 32], b3 = B[k*66 + tx + 48];
        acc[0][0] += a0*b0; acc[0][1] += a0*b1; acc[0][2] += a0*b2; acc[0][3] += a0*b3;
        acc[1][0] += a1*b0; acc[1][1] += a1*b1; acc[1][2] += a1*b2; acc[1][3] += a1*b3;
    }
    #pragma unroll
    for (int i = 0; i < 2; ++i)
        #pragma unroll
        for (int j = 0; j < 4; ++j)
            Cm[(ty + 32*i)*66 + tx + 16*j] = acc[i][j];
}

__global__ void __launch_bounds__(512) k_tail(const float* __restrict__ fc1,
                                              const float* __restrict__ lng,
                                              const float* __restrict__ lnb,
                                              const float* __restrict__ fc2,
                                              const float* __restrict__ xw) {
    extern __shared__ float sm[];
    int blk = blockIdx.x, tid = threadIdx.x;
    float w = 1.0f / (1.0f + expf(-xw[0]));

    if (blk < 4) {
        float* SigN = sm;
        float* P    = sm + 4224;
        float* T1   = sm + 8448;
        float* T2   = sm + 12672;
        __shared__ float mu_s[64];
        __shared__ float s_invtr;
        int g = blk;
        int tx = tid & 15, ty = tid >> 4;

        if (tid < 64) {
            float m = 0.0f;
            #pragma unroll
            for (int ch = 0; ch < 8; ++ch)
                for (int n = 0; n < N_; ++n)
                    m += d_sum8[ch][n * C_ + g * 64 + tid];
            mu_s[tid] = m * (1.0f / MTOT);
        }
        __syncthreads();

        for (int t = 0; t < 8; ++t) {
            int idx = tid + t * 512;
            int d = idx >> 6, e = idx & 63;
            float v = EPSW * (d_gram[g*4096 + idx] - MTOT * mu_s[d] * mu_s[e]);
            if (d == e) v += 1.0f / MTOT;
            T1[d*66 + e] = v;
        }
        __syncthreads();
        if (tid == 0) {
            float tr = 0.0f;
            for (int d = 0; d < 64; ++d) tr += T1[d*66 + d];
            s_invtr = 1.0f / tr;
        }
        __syncthreads();
        float invtr = s_invtr;
        for (int t = 0; t < 8; ++t) {        // P1 = -0.5I + 1.5 SigN (P0 = I)
            int idx = tid + t * 512;
            int d = idx >> 6, e = idx & 63;
            float s = T1[d*66 + e] * invtr;
            SigN[d*66 + e] = s;
            P[d*66 + e] = 1.5f * s + ((d == e) ? -0.5f : 0.0f);
        }
        __syncthreads();
        for (int it = 0; it < 2; ++it) {
            mm64t(T1, P, P, tx, ty);     __syncthreads();
            mm64t(T2, T1, P, tx, ty);    __syncthreads();
            mm64t(T1, T2, SigN, tx, ty); __syncthreads();
            for (int t = 0; t < 8; ++t) {
                int idx = tid + t * 512;
                int d = idx >> 6, e = idx & 63;
                P[d*66 + e] = -0.5f * P[d*66 + e] + 1.5f * T1[d*66 + e];
            }
            __syncthreads();
        }
        for (int t = 0; t < 8; ++t) {
            int idx = tid + t * 512;
            int d = idx >> 6, e = idx & 63;
            d_wP[g*4096 + idx] = w * P[d*66 + e];
        }
    } else {
        int n = blk - 4;
        float* xv  = sm;          // 256
        float* h   = sm + 256;    // 64
        float* red = sm + 320;    // 512
        __shared__ float s_mu, s_inv, s_coef;
        int wi = tid >> 5, lane = tid & 31;

        float acc = 0.0f;
        for (int i = tid; i < N_*C_; i += 512) {
            float s = 0.0f, s2 = 0.0f;
            #pragma unroll
            for (int ch = 0; ch < 8; ++ch) { s += d_sum8[ch][i]; s2 += d_sumsq8[ch][i]; }
            acc += (s2 - s * s * (1.0f / HW_)) * (1.0f / (HW_ - 1));
        }
        red[tid] = acc;
        if (tid < 256) {
            int i = n * C_ + tid;
            float s = 0.0f, s2 = 0.0f;
            #pragma unroll
            for (int ch = 0; ch < 8; ++ch) { s += d_sum8[ch][i]; s2 += d_sumsq8[ch][i]; }
            xv[tid] = (s2 - s * s * (1.0f / HW_)) * (1.0f / (HW_ - 1));
        }
        __syncthreads();
        for (int off = 256; off; off >>= 1) {
            if (tid < off) red[tid] += red[tid + off];
            __syncthreads();
        }
        if (tid == 0)
            s_coef = (1.0f - w) / sqrtf(red[0] * (1.0f / (N_*C_)));

        #pragma unroll
        for (int jj = 0; jj < 4; ++jj) {
            int j = wi * 4 + jj;
            float a = 0.0f;
            #pragma unroll
            for (int s = 0; s < 8; ++s)
                a += fc1[j * C_ + lane + 32 * s] * xv[lane + 32 * s];
            #pragma unroll
            for (int o = 16; o; o >>= 1) a += __shfl_xor_sync(0xffffffffu, a, o);
            if (lane == 0) h[j] = a;
        }
        __syncthreads();

        if (wi == 0) {
            float v0 = h[lane], v1 = h[lane + 32];
            float s = v0 + v1, s2 = v0*v0 + v1*v1;
            #pragma unroll
            for (int o = 16; o; o >>= 1) {
                s  += __shfl_xor_sync(0xffffffffu, s,  o);
                s2 += __shfl_xor_sync(0xffffffffu, s2, o);
            }
            if (lane == 0) {
                float mu = s * (1.0f / D_);
                float var = s2 * (1.0f / D_) - mu * mu;
                s_mu = mu; s_inv = rsqrtf(var + LNEPS);
            }
        }
        __syncthreads();
        if (tid < 64) {
            float v = (h[tid] - s_mu) * s_inv * lng[tid] + lnb[tid];
            h[tid] = v > 0.0f ? v : 0.0f;
        }
        __syncthreads();

        float coef = s_coef;
        #pragma unroll
        for (int k = 0; k < 16; ++k) {
            int c = wi + 16 * k;
            float a = fc2[c * D_ + lane] * h[lane]
                    + fc2[c * D_ + lane + 32] * h[lane + 32];
            #pragma unroll
            for (int o = 16; o; o >>= 1) a += __shfl_xor_sync(0xffffffffu, a, o);
            if (lane == 0) d_a[n * C_ + c] = coef / (1.0f + expf(-a));
        }
    }
}

// ---------------- K3: out = (wP[g] + diag(a[n])) @ x -----------------------
// Position-split double buffer: tile = 64e x 256pos split into half A
// (pos 0..127) and half B (pos 128..255), each 32KB, each filled by 64 x
// 512B cp.async.bulk on its own mbarrier. Compute+store of A overlaps the
// DRAM fill of B, breaking the load->compute phase-lock of co-resident CTAs.
// Per-warp-e body: 2 broadcast float4 m-loads + 1 LDS.128 x + 8 dupf +
// 16 fma2 (acc[8][2]); warp w owns d-rows 8w..8w+7; lane covers 4 positions.
__global__ void __launch_bounds__(256, 2) k_apply(const float* __restrict__ X,
                                                  float* __restrict__ out) {
    extern __shared__ __align__(16) float sm2[];
    float* xs0 = sm2;                  // 64 x 128 floats = 32 KB (half A)
    float* xs1 = sm2 + 8192;           // 64 x 128 floats (half B)
    float* Mt  = sm2 + 16384;          // 64 x 68 floats (Mt[e][d] = M[d][e])
    __shared__ __align__(8) uint64_t mbar0, mbar1;
    int chunk = blockIdx.x, n = blockIdx.y, g = blockIdx.z;
    int tid = threadIdx.x;
    int lane = tid & 31, wrp = tid >> 5;

    const float* base  = X   + ((size_t)n * C_ + (size_t)g * D_) * HW_ + chunk * 256;
    float*       obase = out + ((size_t)n * C_ + (size_t)g * D_) * HW_ + chunk * 256;

    unsigned mb0 = (unsigned)__cvta_generic_to_shared(&mbar0);
    unsigned mb1 = (unsigned)__cvta_generic_to_shared(&mbar1);
    if (tid == 0) {
        asm volatile("mbarrier.init.shared.b64 [%0], 1;" :: "r"(mb0) : "memory");
        asm volatile("mbarrier.init.shared.b64 [%0], 1;" :: "r"(mb1) : "memory");
    }
    __syncthreads();
    if (tid == 0) {
        asm volatile("mbarrier.arrive.expect_tx.shared.b64 _, [%0], %1;"
                     :: "r"(mb0), "r"(32768u) : "memory");
        asm volatile("mbarrier.arrive.expect_tx.shared.b64 _, [%0], %1;"
                     :: "r"(mb1), "r"(32768u) : "memory");
    }
    if (tid < 64) {           // half A: row tid, positions 0..127
        unsigned dst = (unsigned)__cvta_generic_to_shared(xs0 + tid * 128);
        const float* src = base + (size_t)tid * HW_;
        asm volatile(
            "cp.async.bulk.shared::cta.global.mbarrier::complete_tx::bytes "
            "[%0], [%1], %2, [%3];"
            :: "r"(dst), "l"(src), "r"(512u), "r"(mb0) : "memory");
    } else if (tid < 128) {   // half B: row tid-64, positions 128..255
        int c = tid - 64;
        unsigned dst = (unsigned)__cvta_generic_to_shared(xs1 + c * 128);
        const float* src = base + (size_t)c * HW_ + 128;
        asm volatile(
            "cp.async.bulk.shared::cta.global.mbarrier::complete_tx::bytes "
            "[%0], [%1], %2, [%3];"
            :: "r"(dst), "l"(src), "r"(512u), "r"(mb1) : "memory");
    }

    // build Mt while the bulk copies are in flight
    for (int t = 0; t < 16; ++t) {
        int idx = tid + t * 256;
        int d = idx & 63, e = idx >> 6;
        float v = d_wP[g*4096 + d * 64 + e];
        if (d == e) v += d_a[n * C_ + g * 64 + d];
        Mt[e * 68 + d] = v;
    }

    const float4* ma = (const float4*)Mt;        // row stride 17 float4

    // ---- half A ----
    mbar_wait(mb0, 0u);
    __syncthreads();
    {
        ull acc[8][2] = {};
        #pragma unroll 4
        for (int e = 0; e < 64; ++e) {
            float4 m0 = ma[e * 17 + 2 * wrp];
            float4 m1 = ma[e * 17 + 2 * wrp + 1];
            ulonglong2 B = ((const ulonglong2*)(xs0 + e * 128))[lane];
            ull a0 = dupf(m0.x), a1 = dupf(m0.y), a2 = dupf(m0.z), a3 = dupf(m0.w);
            ull a4 = dupf(m1.x), a5 = dupf(m1.y), a6 = dupf(m1.z), a7 = dupf(m1.w);
            fma2(acc[0][0], a0, B.x); fma2(acc[0][1], a0, B.y);
            fma2(acc[1][0], a1, B.x); fma2(acc[1][1], a1, B.y);
            fma2(acc[2][0], a2, B.x); fma2(acc[2][1], a2, B.y);
            fma2(acc[3][0], a3, B.x); fma2(acc[3][1], a3, B.y);
            fma2(acc[4][0], a4, B.x); fma2(acc[4][1], a4, B.y);
            fma2(acc[5][0], a5, B.x); fma2(acc[5][1], a5, B.y);
            fma2(acc[6][0], a6, B.x); fma2(acc[6][1], a6, B.y);
            fma2(acc[7][0], a7, B.x); fma2(acc[7][1], a7, B.y);
        }
        #pragma unroll
        for (int j = 0; j < 8; ++j) {
            int d = 8 * wrp + j;
            float2 r0 = u2f(acc[j][0]), r1 = u2f(acc[j][1]);
            *(float4*)(obase + (size_t)d * HW_ + 4 * lane) =
                make_float4(r0.x, r0.y, r1.x, r1.y);
        }
    }

    // ---- half B ----
    mbar_wait(mb1, 0u);
    {
        ull acc[8][2] = {};
        #pragma unroll 4
        for (int e = 0; e < 64; ++e) {
            float4 m0 = ma[e * 17 + 2 * wrp];
            float4 m1 = ma[e * 17 + 2 * wrp + 1];
            ulonglong2 B = ((const ulonglong2*)(xs1 + e * 128))[lane];
            ull a0 = dupf(m0.x), a1 = dupf(m0.y), a2 = dupf(m0.z), a3 = dupf(m0.w);
            ull a4 = dupf(m1.x), a5 = dupf(m1.y), a6 = dupf(m1.z), a7 = dupf(m1.w);
            fma2(acc[0][0], a0, B.x); fma2(acc[0][1], a0, B.y);
            fma2(acc[1][0], a1, B.x); fma2(acc[1][1], a1, B.y);
            fma2(acc[2][0], a2, B.x); fma2(acc[2][1], a2, B.y);
            fma2(acc[3][0], a3, B.x); fma2(acc[3][1], a3, B.y);
            fma2(acc[4][0], a4, B.x); fma2(acc[4][1], a4, B.y);
            fma2(acc[5][0], a5, B.x); fma2(acc[5][1], a5, B.y);
            fma2(acc[6][0], a6, B.x); fma2(acc[6][1], a6, B.y);
            fma2(acc[7][0], a7, B.x); fma2(acc[7][1], a7, B.y);
        }
        #pragma unroll
        for (int j = 0; j < 8; ++j) {
            int d = 8 * wrp + j;
            float2 r0 = u2f(acc[j][0]), r1 = u2f(acc[j][1]);
            *(float4*)(obase + (size_t)d * HW_ + 128 + 4 * lane) =
                make_float4(r0.x, r0.y, r1.x, r1.y);
        }
    }
}

// ---------------- launch ----------------
extern "C" void kernel_launch(void* const* d_in, const int* in_sizes, int n_in,
                              void* d_out, int out_size) {
    const float* X   = (const float*)d_in[0];
    const float* fc1 = (const float*)d_in[1];
    const float* lng = (const float*)d_in[2];
    const float* lnb = (const float*)d_in[3];
    const float* fc2 = (const float*)d_in[4];
    const float* xw  = (const float*)d_in[5];
    float* out = (float*)d_out;

    static bool attr_set = false;
    if (!attr_set) {
        cudaFuncSetAttribute(k_tail,  cudaFuncAttributeMaxDynamicSharedMemorySize, 69632);
        cudaFuncSetAttribute(k_apply, cudaFuncAttributeMaxDynamicSharedMemorySize, 83968);
        attr_set = true;
    }

    k_zero <<<64, 256>>>();
    k_gram <<<dim3(8, 32, 4), 256>>>(X);
    k_tail <<<36, 512, 69632>>>(fc1, lng, lnb, fc2, xw);
    k_apply<<<dim3(16, 32, 4), 256, 82944>>>(X, out);
}

// round 17
// speedup vs baseline: 1.2677x; 1.2150x over previous
#include <cuda_runtime.h>
#include <math.h>
#include <stdint.h>

#define N_   32
#define C_   256
#define HW_  4096
#define G_   4
#define D_   64
#define MTOT 131072.0f
#define EPSW 1e-5f
#define LNEPS 1e-5f

typedef unsigned long long ull;

__device__ __forceinline__ void fma2(ull& d, ull a, ull b) {
    asm("fma.rn.f32x2 %0, %1, %2, %0;" : "+l"(d) : "l"(a), "l"(b));
}
__device__ __forceinline__ float2 u2f(ull v) {
    float2 r;
    asm("mov.b64 {%0,%1}, %2;" : "=f"(r.x), "=f"(r.y) : "l"(v));
    return r;
}
__device__ __forceinline__ ull dupf(float f) {
    ull r;
    asm("mov.b64 %0, {%1, %1};" : "=l"(r) : "f"(f));
    return r;
}
__device__ __forceinline__ void cpa16(void* sdst, const void* gsrc) {
    unsigned s = (unsigned)__cvta_generic_to_shared(sdst);
    asm volatile("cp.async.ca.shared.global [%0], [%1], 16;" :: "r"(s), "l"(gsrc));
}
#define CP_COMMIT() asm volatile("cp.async.commit_group;")
#define CP_WAIT0()  asm volatile("cp.async.wait_group 0;")

// split pair (a lower, b upper) into bf16 hi word + bf16 lo word
__device__ __forceinline__ void pack2(uint32_t& hw, uint32_t& lw, float a, float b) {
    uint32_t h;
    asm("cvt.rn.satfinite.bf16x2.f32 %0, %1, %2;" : "=r"(h) : "f"(b), "f"(a));
    float ha = __uint_as_float(h << 16);
    float hb = __uint_as_float(h & 0xffff0000u);
    float la = a - ha, lb = b - hb;
    asm("cvt.rn.satfinite.bf16x2.f32 %0, %1, %2;" : "=r"(lw) : "f"(lb), "f"(la));
    hw = h;
}

#define LDM4(r, addr)                                                          \
    asm volatile("ldmatrix.sync.aligned.m8n8.x4.shared.b16 {%0,%1,%2,%3}, [%4];" \
                 : "=r"((r)[0]), "=r"((r)[1]), "=r"((r)[2]), "=r"((r)[3])      \
                 : "r"(addr))

#define MMA16816(dd, a, bb0, bb1)                                              \
    asm volatile("mma.sync.aligned.m16n8k16.row.col.f32.bf16.bf16.f32 "        \
                 "{%0,%1,%2,%3}, {%4,%5,%6,%7}, {%8,%9}, {%0,%1,%2,%3};"       \
                 : "+f"((dd)[0]), "+f"((dd)[1]), "+f"((dd)[2]), "+f"((dd)[3])  \
                 : "r"((a)[0]), "r"((a)[1]), "r"((a)[2]), "r"((a)[3]),         \
                   "r"(bb0), "r"(bb1))

// ---------------- device scratch ----------------
__device__ float d_sum8  [8][N_*C_];
__device__ float d_sumsq8[8][N_*C_];
__device__ float d_gram [G_*D_*D_];
__device__ float d_a    [N_*C_];
__device__ float d_wP   [G_*D_*D_];

// ---------------- K0: zero gram accumulators ----------------
__global__ void k_zero() {
    int i = blockIdx.x * blockDim.x + threadIdx.x;
    if (i < G_*D_*D_) d_gram[i] = 0.0f;
}

// ---------------- K1: gram via mma.sync bf16-split + fused row stats -------
// grid (chunk=8, n=32, g=4), 256 thr (8 warps). 8 tiles of 64ch x 64pos.
// Split x = hi + lo (bf16); Gram += Ah*Bh + Ah*Bl + Al*Bh (ll ~2^-18 dropped).
// Tiles in smem as bf16, rows padded to 72 elems (144B: bank stride 4 ->
// ldmatrix + STS.64 conflict-free). Warp w: rows (w&3)*16, cols (w>>2)*32;
// reg-resident f32 accumulators (4 n8-frags). Software pipeline:
// LDG t+1 -> mma t -> convert/STS t+1 (double buffer).
__global__ void __launch_bounds__(256, 3) k_gram(const float* __restrict__ X) {
    __shared__ __align__(16) unsigned short hiT[2][64 * 72];  // 2 x 9216 B
    __shared__ __align__(16) unsigned short loT[2][64 * 72];
    int chunk = blockIdx.x, n = blockIdx.y, g = blockIdx.z;
    int tid = threadIdx.x;
    int lane = tid & 31, w = tid >> 5;
    const float* base = X + ((size_t)n * C_ + (size_t)g * D_) * HW_ + chunk * 512;

    int c_low = tid >> 4, s4 = tid & 15;    // thread covers channels 16k+c_low, seg s4

    float d[4][4];
    #pragma unroll
    for (int i = 0; i < 4; ++i) { d[i][0]=0.f; d[i][1]=0.f; d[i][2]=0.f; d[i][3]=0.f; }
    float ssum[4] = {0.f,0.f,0.f,0.f}, ssq[4] = {0.f,0.f,0.f,0.f};

    uint32_t hiB[2] = { (uint32_t)__cvta_generic_to_shared(&hiT[0][0]),
                        (uint32_t)__cvta_generic_to_shared(&hiT[1][0]) };
    uint32_t loB[2] = { (uint32_t)__cvta_generic_to_shared(&loT[0][0]),
                        (uint32_t)__cvta_generic_to_shared(&loT[1][0]) };

    int wrow = (w & 3) * 16, wcol = (w >> 2) * 32;
    uint32_t aoff  = (uint32_t)(wrow + (lane & 15)) * 144u + (uint32_t)(lane >> 4) * 16u;
    uint32_t boff0 = (uint32_t)(wcol + ((lane >> 4) * 8) + (lane & 7)) * 144u
                   + (uint32_t)((lane >> 3) & 1) * 16u;
    uint32_t boff1 = boff0 + 16u * 144u;
    uint32_t stoff = 0;  // set per channel below

    {   // prologue: tile 0 -> buf 0
        #pragma unroll
        for (int k = 0; k < 4; ++k) {
            int c = 16 * k + c_low;
            float4 v = *(const float4*)(base + (size_t)c * HW_ + s4 * 4);
            ssum[k] += v.x + v.y + v.z + v.w;
            ssq[k]  += v.x*v.x + v.y*v.y + v.z*v.z + v.w*v.w;
            uint32_t h0,l0,h1,l1;
            pack2(h0, l0, v.x, v.y);
            pack2(h1, l1, v.z, v.w);
            uint32_t off = (uint32_t)c * 144u + (uint32_t)s4 * 8u;
            *(uint2*)((char*)&hiT[0][0] + off) = make_uint2(h0, h1);
            *(uint2*)((char*)&loT[0][0] + off) = make_uint2(l0, l1);
        }
    }

    for (int t = 0; t < 8; ++t) {
        __syncthreads();                       // STS of tile t visible
        int buf = t & 1;
        float4 v[4];
        if (t < 7) {
            const float* src = base + (t + 1) * 64;
            #pragma unroll
            for (int k = 0; k < 4; ++k) {
                int c = 16 * k + c_low;
                v[k] = *(const float4*)(src + (size_t)c * HW_ + s4 * 4);
            }
        }
        uint32_t hib = hiB[buf], lob = loB[buf];
        #pragma unroll
        for (int ks = 0; ks < 4; ++ks) {
            uint32_t kb = (uint32_t)ks * 32u;
            uint32_t ah[4], al[4], bh0[4], bh1[4], bl0[4], bl1[4];
            LDM4(ah,  hib + aoff  + kb);
            LDM4(al,  lob + aoff  + kb);
            LDM4(bh0, hib + boff0 + kb);
            LDM4(bh1, hib + boff1 + kb);
            LDM4(bl0, lob + boff0 + kb);
            LDM4(bl1, lob + boff1 + kb);
            MMA16816(d[0], ah, bh0[0], bh0[1]);
            MMA16816(d[0], ah, bl0[0], bl0[1]);
            MMA16816(d[0], al, bh0[0], bh0[1]);
            MMA16816(d[1], ah, bh0[2], bh0[3]);
            MMA16816(d[1], ah, bl0[2], bl0[3]);
            MMA16816(d[1], al, bh0[2], bh0[3]);
            MMA16816(d[2], ah, bh1[0], bh1[1]);
            MMA16816(d[2], ah, bl1[0], bl1[1]);
            MMA16816(d[2], al, bh1[0], bh1[1]);
            MMA16816(d[3], ah, bh1[2], bh1[3]);
            MMA16816(d[3], ah, bl1[2], bl1[3]);
            MMA16816(d[3], al, bh1[2], bh1[3]);
        }
        if (t < 7) {                           // convert + STS tile t+1 -> buf^1
            int nb = buf ^ 1;
            #pragma unroll
            for (int k = 0; k < 4; ++k) {
                int c = 16 * k + c_low;
                ssum[k] += v[k].x + v[k].y + v[k].z + v[k].w;
                ssq[k]  += v[k].x*v[k].x + v[k].y*v[k].y + v[k].z*v[k].z + v[k].w*v[k].w;
                uint32_t h0,l0,h1,l1;
                pack2(h0, l0, v[k].x, v[k].y);
                pack2(h1, l1, v[k].z, v[k].w);
                uint32_t off = (uint32_t)c * 144u + (uint32_t)s4 * 8u;
                *(uint2*)((char*)&hiT[nb][0] + off) = make_uint2(h0, h1);
                *(uint2*)((char*)&loT[nb][0] + off) = make_uint2(l0, l1);
            }
        }
    }

    // row stats: reduce over the 16 lanes sharing each channel (s4 = lane&15)
    #pragma unroll
    for (int k = 0; k < 4; ++k) {
        #pragma unroll
        for (int o = 8; o; o >>= 1) {
            ssum[k] += __shfl_xor_sync(0xffffffffu, ssum[k], o);
            ssq[k]  += __shfl_xor_sync(0xffffffffu, ssq[k],  o);
        }
    }
    if (s4 == 0) {
        #pragma unroll
        for (int k = 0; k < 4; ++k) {
            d_sum8  [chunk][n * C_ + g * 64 + 16 * k + c_low] = ssum[k];
            d_sumsq8[chunk][n * C_ + g * 64 + 16 * k + c_low] = ssq[k];
        }
    }

    // gram epilogue: D-frag -> atomics. rows wrow+(lane>>2), +8; cols wcol+f*8+(lane&3)*2
    float* gp = d_gram + g * 4096;
    int r0 = wrow + (lane >> 2);
    int cb = wcol + (lane & 3) * 2;
    #pragma unroll
    for (int f = 0; f < 4; ++f) {
        atomicAdd(&gp[r0 * 64 + cb + f * 8],           d[f][0]);
        atomicAdd(&gp[r0 * 64 + cb + f * 8 + 1],       d[f][1]);
        atomicAdd(&gp[(r0 + 8) * 64 + cb + f * 8],     d[f][2]);
        atomicAdd(&gp[(r0 + 8) * 64 + cb + f * 8 + 1], d[f][3]);
    }
}

// ---------------- K2: fused newton (blocks 0-3) + mlp (blocks 4-35) --------
__device__ __forceinline__ void mm64t(float* Cm, const float* A, const float* B,
                                      int tx, int ty) {
    float acc[2][4] = {};
    #pragma unroll 4
    for (int k = 0; k < 64; ++k) {
        float a0 = A[ty*66 + k], a1 = A[(ty + 32)*66 + k];
        float b0 = B[k*66 + tx],      b1 = B[k*66 + tx + 16];
        float b2 = B[k*66 + tx + 32], b3 = B[k*66 + tx + 48];
        acc[0][0] += a0*b0; acc[0][1] += a0*b1; acc[0][2] += a0*b2; acc[0][3] += a0*b3;
        acc[1][0] += a1*b0; acc[1][1] += a1*b1; acc[1][2] += a1*b2; acc[1][3] += a1*b3;
    }
    #pragma unroll
    for (int i = 0; i < 2; ++i)
        #pragma unroll
        for (int j = 0; j < 4; ++j)
            Cm[(ty + 32*i)*66 + tx + 16*j] = acc[i][j];
}

__global__ void __launch_bounds__(512) k_tail(const float* __restrict__ fc1,
                                              const float* __restrict__ lng,
                                              const float* __restrict__ lnb,
                                              const float* __restrict__ fc2,
                                              const float* __restrict__ xw) {
    extern __shared__ float sm[];
    int blk = blockIdx.x, tid = threadIdx.x;
    float w = 1.0f / (1.0f + expf(-xw[0]));

    if (blk < 4) {
        float* SigN = sm;
        float* P    = sm + 4224;
        float* T1   = sm + 8448;
        float* T2   = sm + 12672;
        __shared__ float mu_s[64];
        __shared__ float s_invtr;
        int g = blk;
        int tx = tid & 15, ty = tid >> 4;

        if (tid < 64) {
            float m = 0.0f;
            #pragma unroll
            for (int ch = 0; ch < 8; ++ch)
                for (int n = 0; n < N_; ++n)
                    m += d_sum8[ch][n * C_ + g * 64 + tid];
            mu_s[tid] = m * (1.0f / MTOT);
        }
        __syncthreads();

        for (int t = 0; t < 8; ++t) {
            int idx = tid + t * 512;
            int d = idx >> 6, e = idx & 63;
            float v = EPSW * (d_gram[g*4096 + idx] - MTOT * mu_s[d] * mu_s[e]);
            if (d == e) v += 1.0f / MTOT;
            T1[d*66 + e] = v;
        }
        __syncthreads();
        if (tid == 0) {
            float tr = 0.0f;
            for (int d = 0; d < 64; ++d) tr += T1[d*66 + d];
            s_invtr = 1.0f / tr;
        }
        __syncthreads();
        float invtr = s_invtr;
        for (int t = 0; t < 8; ++t) {        // P1 = -0.5I + 1.5 SigN (P0 = I)
            int idx = tid + t * 512;
            int d = idx >> 6, e = idx & 63;
            float s = T1[d*66 + e] * invtr;
            SigN[d*66 + e] = s;
            P[d*66 + e] = 1.5f * s + ((d == e) ? -0.5f : 0.0f);
        }
        __syncthreads();
        for (int it = 0; it < 2; ++it) {
            mm64t(T1, P, P, tx, ty);     __syncthreads();
            mm64t(T2, T1, P, tx, ty);    __syncthreads();
            mm64t(T1, T2, SigN, tx, ty); __syncthreads();
            for (int t = 0; t < 8; ++t) {
                int idx = tid + t * 512;
                int d = idx >> 6, e = idx & 63;
                P[d*66 + e] = -0.5f * P[d*66 + e] + 1.5f * T1[d*66 + e];
            }
            __syncthreads();
        }
        for (int t = 0; t < 8; ++t) {
            int idx = tid + t * 512;
            int d = idx >> 6, e = idx & 63;
            d_wP[g*4096 + idx] = w * P[d*66 + e];
        }
    } else {
        int n = blk - 4;
        float* xv  = sm;          // 256
        float* h   = sm + 256;    // 64
        float* red = sm + 320;    // 512
        __shared__ float s_mu, s_inv, s_coef;
        int wi = tid >> 5, lane = tid & 31;

        float acc = 0.0f;
        for (int i = tid; i < N_*C_; i += 512) {
            float s = 0.0f, s2 = 0.0f;
            #pragma unroll
            for (int ch = 0; ch < 8; ++ch) { s += d_sum8[ch][i]; s2 += d_sumsq8[ch][i]; }
            acc += (s2 - s * s * (1.0f / HW_)) * (1.0f / (HW_ - 1));
        }
        red[tid] = acc;
        if (tid < 256) {
            int i = n * C_ + tid;
            float s = 0.0f, s2 = 0.0f;
            #pragma unroll
            for (int ch = 0; ch < 8; ++ch) { s += d_sum8[ch][i]; s2 += d_sumsq8[ch][i]; }
            xv[tid] = (s2 - s * s * (1.0f / HW_)) * (1.0f / (HW_ - 1));
        }
        __syncthreads();
        for (int off = 256; off; off >>= 1) {
            if (tid < off) red[tid] += red[tid + off];
            __syncthreads();
        }
        if (tid == 0)
            s_coef = (1.0f - w) / sqrtf(red[0] * (1.0f / (N_*C_)));

        #pragma unroll
        for (int jj = 0; jj < 4; ++jj) {
            int j = wi * 4 + jj;
            float a = 0.0f;
            #pragma unroll
            for (int s = 0; s < 8; ++s)
                a += fc1[j * C_ + lane + 32 * s] * xv[lane + 32 * s];
            #pragma unroll
            for (int o = 16; o; o >>= 1) a += __shfl_xor_sync(0xffffffffu, a, o);
            if (lane == 0) h[j] = a;
        }
        __syncthreads();

        if (wi == 0) {
            float v0 = h[lane], v1 = h[lane + 32];
            float s = v0 + v1, s2 = v0*v0 + v1*v1;
            #pragma unroll
            for (int o = 16; o; o >>= 1) {
                s  += __shfl_xor_sync(0xffffffffu, s,  o);
                s2 += __shfl_xor_sync(0xffffffffu, s2, o);
            }
            if (lane == 0) {
                float mu = s * (1.0f / D_);
                float var = s2 * (1.0f / D_) - mu * mu;
                s_mu = mu; s_inv = rsqrtf(var + LNEPS);
            }
        }
        __syncthreads();
        if (tid < 64) {
            float v = (h[tid] - s_mu) * s_inv * lng[tid] + lnb[tid];
            h[tid] = v > 0.0f ? v : 0.0f;
        }
        __syncthreads();

        float coef = s_coef;
        #pragma unroll
        for (int k = 0; k < 16; ++k) {
            int c = wi + 16 * k;
            float a = fc2[c * D_ + lane] * h[lane]
                    + fc2[c * D_ + lane + 32] * h[lane + 32];
            #pragma unroll
            for (int o = 16; o; o >>= 1) a += __shfl_xor_sync(0xffffffffu, a, o);
            if (lane == 0) d_a[n * C_ + c] = coef / (1.0f + expf(-a));
        }
    }
}

// ---------------- K3: out = (wP[g] + diag(a[n])) @ x -----------------------
// Round-12 version exactly (best measured: 107.6us).
__global__ void __launch_bounds__(256, 2) k_apply(const float* __restrict__ X,
                                                  float* __restrict__ out) {
    extern __shared__ __align__(16) float sm2[];
    float* xs = sm2;                   // 64 x 256 floats = 64 KB
    float* Mt = sm2 + 16384;           // 64 x 68 floats (Mt[e][d] = M[d][e])
    int chunk = blockIdx.x, n = blockIdx.y, g = blockIdx.z;
    int tid = threadIdx.x;
    int lane = tid & 31, wrp = tid >> 5;

    const float* base  = X   + ((size_t)n * C_ + (size_t)g * D_) * HW_ + chunk * 256;
    float*       obase = out + ((size_t)n * C_ + (size_t)g * D_) * HW_ + chunk * 256;

    #pragma unroll
    for (int k = 0; k < 16; ++k) {
        int pos = tid + k * 256;
        int c = pos >> 6, s4 = pos & 63;
        cpa16(xs + c * 256 + s4 * 4, base + (size_t)c * HW_ + s4 * 4);
    }
    CP_COMMIT();

    for (int t = 0; t < 16; ++t) {
        int idx = tid + t * 256;
        int d = idx & 63, e = idx >> 6;
        float v = d_wP[g*4096 + d * 64 + e];
        if (d == e) v += d_a[n * C_ + g * 64 + d];
        Mt[e * 68 + d] = v;
    }

    CP_WAIT0();
    __syncthreads();

    ull acc[8][4] = {};
    const float4* ma = (const float4*)Mt;        // row stride 17 float4
    #pragma unroll 4
    for (int e = 0; e < 64; ++e) {
        float4 m0 = ma[e * 17 + 2 * wrp];
        float4 m1 = ma[e * 17 + 2 * wrp + 1];
        const ulonglong2* xrow = (const ulonglong2*)(xs + e * 256);
        ulonglong2 B0 = xrow[lane];
        ulonglong2 B1 = xrow[lane + 32];
        ull a0 = dupf(m0.x), a1 = dupf(m0.y), a2 = dupf(m0.z), a3 = dupf(m0.w);
        ull a4 = dupf(m1.x), a5 = dupf(m1.y), a6 = dupf(m1.z), a7 = dupf(m1.w);
        fma2(acc[0][0], a0, B0.x); fma2(acc[0][1], a0, B0.y);
        fma2(acc[0][2], a0, B1.x); fma2(acc[0][3], a0, B1.y);
        fma2(acc[1][0], a1, B0.x); fma2(acc[1][1], a1, B0.y);
        fma2(acc[1][2], a1, B1.x); fma2(acc[1][3], a1, B1.y);
        fma2(acc[2][0], a2, B0.x); fma2(acc[2][1], a2, B0.y);
        fma2(acc[2][2], a2, B1.x); fma2(acc[2][3], a2, B1.y);
        fma2(acc[3][0], a3, B0.x); fma2(acc[3][1], a3, B0.y);
        fma2(acc[3][2], a3, B1.x); fma2(acc[3][3], a3, B1.y);
        fma2(acc[4][0], a4, B0.x); fma2(acc[4][1], a4, B0.y);
        fma2(acc[4][2], a4, B1.x); fma2(acc[4][3], a4, B1.y);
        fma2(acc[5][0], a5, B0.x); fma2(acc[5][1], a5, B0.y);
        fma2(acc[5][2], a5, B1.x); fma2(acc[5][3], a5, B1.y);
        fma2(acc[6][0], a6, B0.x); fma2(acc[6][1], a6, B0.y);
        fma2(acc[6][2], a6, B1.x); fma2(acc[6][3], a6, B1.y);
        fma2(acc[7][0], a7, B0.x); fma2(acc[7][1], a7, B0.y);
        fma2(acc[7][2], a7, B1.x); fma2(acc[7][3], a7, B1.y);
    }

    #pragma unroll
    for (int j = 0; j < 8; ++j) {
        int d = 8 * wrp + j;
        float* drow = obase + (size_t)d * HW_;
        float2 r0 = u2f(acc[j][0]), r1 = u2f(acc[j][1]);
        float2 r2 = u2f(acc[j][2]), r3 = u2f(acc[j][3]);
        *(float4*)(drow + 4 * lane)       = make_float4(r0.x, r0.y, r1.x, r1.y);
        *(float4*)(drow + 128 + 4 * lane) = make_float4(r2.x, r2.y, r3.x, r3.y);
    }
}

// ---------------- launch ----------------
extern "C" void kernel_launch(void* const* d_in, const int* in_sizes, int n_in,
                              void* d_out, int out_size) {
    const float* X   = (const float*)d_in[0];
    const float* fc1 = (const float*)d_in[1];
    const float* lng = (const float*)d_in[2];
    const float* lnb = (const float*)d_in[3];
    const float* fc2 = (const float*)d_in[4];
    const float* xw  = (const float*)d_in[5];
    float* out = (float*)d_out;

    static bool attr_set = false;
    if (!attr_set) {
        cudaFuncSetAttribute(k_tail,  cudaFuncAttributeMaxDynamicSharedMemorySize, 69632);
        cudaFuncSetAttribute(k_apply, cudaFuncAttributeMaxDynamicSharedMemorySize, 83968);
        attr_set = true;
    }

    k_zero <<<64, 256>>>();
    k_gram <<<dim3(8, 32, 4), 256>>>(X);
    k_tail <<<36, 512, 69632>>>(fc1, lng, lnb, fc2, xw);
    k_apply<<<dim3(16, 32, 4), 256, 82944>>>(X, out);
}